// round 10
// baseline (speedup 1.0000x reference)
#include <cuda_runtime.h>
#include <cstdint>

// ---------------------------------------------------------------------------
// Transformer encoder: split-bf16 mma.sync GEMMs (R5 config) + fused flash
// attention with LPT (longest-first) CTA ordering.
// B=4, T=1024, C=1024, H=16, HD=64, FF=4096, L=4
// ---------------------------------------------------------------------------

#define NTOK   4096
#define CDIM   1024
#define QKVD   1536
#define KVOFF  1024
#define VOFF   1280
#define FFD    4096
#define TT     1024
#define NBH    64
#define HDIM   64
#define NLAYER 4

// ---- fp32 scratch ----
__device__ float g_x[NTOK * CDIM];
__device__ float g_y[NTOK * CDIM];

// ---- split-bf16 activation planes ----
__device__ uint16_t g_xh[NTOK * CDIM];
__device__ uint16_t g_xl[NTOK * CDIM];
__device__ uint16_t g_qh[NTOK * QKVD];
__device__ uint16_t g_ql[NTOK * QKVD];
__device__ uint16_t g_oh[NTOK * CDIM];
__device__ uint16_t g_ol[NTOK * CDIM];
__device__ uint16_t g_fh[NTOK * FFD];
__device__ uint16_t g_fl[NTOK * FFD];

// ---- split-bf16 weight planes ----
__device__ uint16_t g_wih[NLAYER * QKVD * CDIM];
__device__ uint16_t g_wil[NLAYER * QKVD * CDIM];
__device__ uint16_t g_woh[NLAYER * CDIM * CDIM];
__device__ uint16_t g_wol[NLAYER * CDIM * CDIM];
__device__ uint16_t g_w1h[NLAYER * FFD * CDIM];
__device__ uint16_t g_w1l[NLAYER * FFD * CDIM];
__device__ uint16_t g_w2h[NLAYER * CDIM * FFD];
__device__ uint16_t g_w2l[NLAYER * CDIM * FFD];

// ===========================================================================
// helpers
// ===========================================================================
__device__ __forceinline__ uint32_t smem_u32(const void* p) {
    uint32_t a;
    asm("{ .reg .u64 t; cvta.to.shared.u64 t, %1; cvt.u32.u64 %0, t; }"
        : "=r"(a) : "l"(p));
    return a;
}
__device__ __forceinline__ uint32_t f2bf_rn(float x) {
    uint32_t u = __float_as_uint(x);
    return (u + 0x7FFFu + ((u >> 16) & 1u)) >> 16;
}
__device__ __forceinline__ float bf2f(uint32_t h) {
    return __uint_as_float(h << 16);
}
__device__ __forceinline__ uint32_t pack_split(float a, float b, uint32_t* lo) {
    uint32_t ha = f2bf_rn(a), hb = f2bf_rn(b);
    *lo = f2bf_rn(a - bf2f(ha)) | (f2bf_rn(b - bf2f(hb)) << 16);
    return ha | (hb << 16);
}

#define CP16(dst, src) \
    asm volatile("cp.async.cg.shared.global [%0], [%1], 16;" \
                 :: "r"(dst), "l"(src))
#define CP_COMMIT() asm volatile("cp.async.commit_group;" ::: "memory")
#define CP_WAIT0()  asm volatile("cp.async.wait_group 0;" ::: "memory")
#define CP_WAIT1()  asm volatile("cp.async.wait_group 1;" ::: "memory")

__device__ __forceinline__ void ldsm4(uint32_t* r, uint32_t addr) {
    asm volatile("ldmatrix.sync.aligned.m8n8.x4.shared.b16 {%0,%1,%2,%3}, [%4];"
                 : "=r"(r[0]), "=r"(r[1]), "=r"(r[2]), "=r"(r[3]) : "r"(addr));
}
__device__ __forceinline__ void ldsm4t(uint32_t* r, uint32_t addr) {
    asm volatile("ldmatrix.sync.aligned.m8n8.x4.trans.shared.b16 {%0,%1,%2,%3}, [%4];"
                 : "=r"(r[0]), "=r"(r[1]), "=r"(r[2]), "=r"(r[3]) : "r"(addr));
}
__device__ __forceinline__ void mma_bf16(float* c, const uint32_t* a,
                                         const uint32_t* b) {
    asm volatile(
        "mma.sync.aligned.m16n8k16.row.col.f32.bf16.bf16.f32 "
        "{%0,%1,%2,%3}, {%4,%5,%6,%7}, {%8,%9}, {%0,%1,%2,%3};"
        : "+f"(c[0]), "+f"(c[1]), "+f"(c[2]), "+f"(c[3])
        : "r"(a[0]), "r"(a[1]), "r"(a[2]), "r"(a[3]), "r"(b[0]), "r"(b[1]));
}

// ===========================================================================
// split kernels (weights merged into two launches so the QKV GEMM lands in
// ncu's capture slot)
// ===========================================================================
__global__ __launch_bounds__(256) void split2_kernel(
    const float4* __restrict__ s1, int n1blocks,
    uint2* __restrict__ h1, uint2* __restrict__ l1,
    const float4* __restrict__ s2,
    uint2* __restrict__ h2, uint2* __restrict__ l2)
{
    int blk = blockIdx.x;
    const float4* src; uint2 *hi, *lo; size_t i;
    if (blk < n1blocks) {
        i = (size_t)blk * 256 + threadIdx.x; src = s1; hi = h1; lo = l1;
    } else {
        i = (size_t)(blk - n1blocks) * 256 + threadIdx.x;
        src = s2; hi = h2; lo = l2;
    }
    float4 v = src[i];
    uint32_t l0, l1r;
    uint32_t h0 = pack_split(v.x, v.y, &l0);
    uint32_t h1r = pack_split(v.z, v.w, &l1r);
    hi[i] = make_uint2(h0, h1r);
    lo[i] = make_uint2(l0, l1r);
}

__global__ __launch_bounds__(256) void copy_in_kernel(
    const float4* __restrict__ src, float4* __restrict__ dst,
    uint2* __restrict__ hi, uint2* __restrict__ lo)
{
    size_t i = (size_t)blockIdx.x * 256 + threadIdx.x;
    float4 v = src[i];
    dst[i] = v;
    uint32_t l0, l1;
    uint32_t h0 = pack_split(v.x, v.y, &l0);
    uint32_t h1 = pack_split(v.z, v.w, &l1);
    hi[i] = make_uint2(h0, h1);
    lo[i] = make_uint2(l0, l1);
}

// ===========================================================================
// mma.sync GEMM (R5 configuration): out[m,n] = sum_k A[m,k]*W[n,k] + bias[n]
// CTA 128x128, warp tile 64x32, BK=32, 2-stage, split-bf16 x3 products.
// ===========================================================================
#define G_STAGE 40960
#define G_SMEM  (2 * G_STAGE)

__device__ __forceinline__ void gemm_issue(
    uint32_t sb, int buf, int kb,
    const uint16_t* Ah, const uint16_t* Al,
    const uint16_t* Wh, const uint16_t* Wl,
    int row0, int col0, int K, int tid)
{
    uint32_t dst = sb + (uint32_t)buf * G_STAGE;
    int ch = tid & 3;
    size_t kbase = (size_t)kb * 32 + ch * 8;
#pragma unroll
    for (int i = 0; i < 2; i++) {
        int r = (tid >> 2) + i * 64;
        uint32_t so = (uint32_t)(r * 80 + ch * 16);
        CP16(dst + so,         Ah + (size_t)(row0 + r) * K + kbase);
        CP16(dst + 10240 + so, Al + (size_t)(row0 + r) * K + kbase);
        CP16(dst + 20480 + so, Wh + (size_t)(col0 + r) * K + kbase);
        CP16(dst + 30720 + so, Wl + (size_t)(col0 + r) * K + kbase);
    }
}

template <bool RELU, bool SPLIT>
__global__ __launch_bounds__(256) void gemm_mma_kernel(
    const uint16_t* __restrict__ Ah, const uint16_t* __restrict__ Al,
    const uint16_t* __restrict__ Wh, const uint16_t* __restrict__ Wl,
    const float* __restrict__ bias, float* __restrict__ outf,
    uint32_t* __restrict__ outh, uint32_t* __restrict__ outl,
    int K, int N)
{
    extern __shared__ char sm[];
    const uint32_t sb = smem_u32(sm);
    const int tid = threadIdx.x, lane = tid & 31, wid = tid >> 5;
    const int row0 = blockIdx.y << 7, col0 = blockIdx.x << 7;
    const int m0 = (wid >> 2) << 6;
    const int n0 = (wid & 3) << 5;

    const uint32_t aoff = (uint32_t)((m0 + (lane & 15)) * 80 + (lane >> 4) * 16);
    const uint32_t boff = (uint32_t)((n0 + (lane & 7) + ((lane >> 4) & 1) * 8) * 80
                                     + ((lane >> 3) & 1) * 16);

    float acc[4][4][4];
#pragma unroll
    for (int mi = 0; mi < 4; mi++)
#pragma unroll
        for (int ni = 0; ni < 4; ni++)
#pragma unroll
            for (int q = 0; q < 4; q++) acc[mi][ni][q] = 0.f;

    const int nkb = K >> 5;
    gemm_issue(sb, 0, 0, Ah, Al, Wh, Wl, row0, col0, K, tid);
    CP_COMMIT();

    for (int kb = 0; kb < nkb; kb++) {
        CP_WAIT0();
        __syncthreads();
        if (kb + 1 < nkb) {
            gemm_issue(sb, (kb + 1) & 1, kb + 1, Ah, Al, Wh, Wl,
                       row0, col0, K, tid);
            CP_COMMIT();
        }
        const uint32_t base = sb + (uint32_t)(kb & 1) * G_STAGE;
#pragma unroll
        for (int ks = 0; ks < 2; ks++) {
            uint32_t fah[4][4], fal[4][4], fbh[2][4], fbl[2][4];
#pragma unroll
            for (int mi = 0; mi < 4; mi++) {
                uint32_t off = aoff + mi * 1280 + ks * 32;
                ldsm4(fah[mi], base + off);
                ldsm4(fal[mi], base + 10240 + off);
            }
#pragma unroll
            for (int nj = 0; nj < 2; nj++) {
                uint32_t off = boff + nj * 1280 + ks * 32;
                ldsm4(fbh[nj], base + 20480 + off);
                ldsm4(fbl[nj], base + 30720 + off);
            }
#pragma unroll
            for (int mi = 0; mi < 4; mi++) {
#pragma unroll
                for (int ni = 0; ni < 4; ni++) {
                    const uint32_t* bh = &fbh[ni >> 1][(ni & 1) * 2];
                    const uint32_t* bl = &fbl[ni >> 1][(ni & 1) * 2];
                    mma_bf16(acc[mi][ni], fah[mi], bh);
                    mma_bf16(acc[mi][ni], fah[mi], bl);
                    mma_bf16(acc[mi][ni], fal[mi], bh);
                }
            }
        }
        __syncthreads();
    }

#pragma unroll
    for (int mi = 0; mi < 4; mi++) {
        int row = row0 + m0 + mi * 16 + (lane >> 2);
#pragma unroll
        for (int ni = 0; ni < 4; ni++) {
            int col = col0 + n0 + ni * 8 + (lane & 3) * 2;
            float b0 = __ldg(&bias[col]), b1 = __ldg(&bias[col + 1]);
            float v00 = acc[mi][ni][0] + b0, v01 = acc[mi][ni][1] + b1;
            float v10 = acc[mi][ni][2] + b0, v11 = acc[mi][ni][3] + b1;
            if (RELU) {
                v00 = fmaxf(v00, 0.f); v01 = fmaxf(v01, 0.f);
                v10 = fmaxf(v10, 0.f); v11 = fmaxf(v11, 0.f);
            }
            if (SPLIT) {
                uint32_t l0, l1;
                uint32_t h0 = pack_split(v00, v01, &l0);
                uint32_t h1 = pack_split(v10, v11, &l1);
                size_t i0 = ((size_t)row * N + col) >> 1;
                size_t i1 = ((size_t)(row + 8) * N + col) >> 1;
                outh[i0] = h0; outl[i0] = l0;
                outh[i1] = h1; outl[i1] = l1;
            } else {
                *reinterpret_cast<float2*>(&outf[(size_t)row * N + col]) =
                    make_float2(v00, v01);
                *reinterpret_cast<float2*>(&outf[(size_t)(row + 8) * N + col]) =
                    make_float2(v10, v11);
            }
        }
    }
}

// ===========================================================================
// fused flash attention, LPT ordering: heavy q-tiles launch first.
// ===========================================================================
#define SKS      144
#define FL_QL    18432
#define FL_ST0   36864
#define FL_STAGE 36864
#define FL_SMEM  (FL_ST0 + 2 * FL_STAGE)
#define SCL      0.1803368801111204f   // 0.125 * log2(e)

__device__ __forceinline__ void flash_issue_kv(
    uint32_t sb, int buf, int s0, int b, int kvh, int tid,
    const uint16_t* Qhp, const uint16_t* Qlp)
{
    uint32_t dst = sb + FL_ST0 + (uint32_t)buf * FL_STAGE;
    int r = tid >> 2;
    int c0 = (tid & 3) * 2;
    size_t rowoff = (size_t)(b * TT + s0 + r) * QKVD;
    const uint16_t* kh = Qhp + rowoff + KVOFF + kvh * HDIM;
    const uint16_t* kl = Qlp + rowoff + KVOFF + kvh * HDIM;
    const uint16_t* vh = Qhp + rowoff + VOFF + kvh * HDIM;
    const uint16_t* vl = Qlp + rowoff + VOFF + kvh * HDIM;
    uint32_t so = (uint32_t)(r * SKS + c0 * 16);
#pragma unroll
    for (int c = 0; c < 2; c++) {
        CP16(dst + so + c * 16,         kh + (c0 + c) * 8);
        CP16(dst + 9216 + so + c * 16,  kl + (c0 + c) * 8);
        CP16(dst + 18432 + so + c * 16, vh + (c0 + c) * 8);
        CP16(dst + 27648 + so + c * 16, vl + (c0 + c) * 8);
    }
}

__global__ __launch_bounds__(256) void flash_kernel(
    const uint16_t* __restrict__ Qhp, const uint16_t* __restrict__ Qlp,
    uint32_t* __restrict__ Oh, uint32_t* __restrict__ Ol)
{
    extern __shared__ char sm[];
    const uint32_t sb = smem_u32(sm);
    const int tid = threadIdx.x, lane = tid & 31, wid = tid >> 5;
    const int bh = blockIdx.y, b = bh >> 4, hq = bh & 15, kvh = hq & 3;
    // LPT: reverse x so 16-iter CTAs launch first, short CTAs pack the tail
    const int xr = (int)gridDim.x - 1 - (int)blockIdx.x;
    const int q0 = xr * 128;
    const int iters = 2 * (xr + 1);

    {
        int r = tid >> 1;
        int cb = (tid & 1) * 4;
        size_t src = (size_t)(b * TT + q0 + r) * QKVD + hq * HDIM + cb * 8;
        uint32_t d0 = sb + r * SKS + cb * 16;
#pragma unroll
        for (int c = 0; c < 4; c++) {
            CP16(d0 + c * 16,          Qhp + src + c * 8);
            CP16(d0 + FL_QL + c * 16,  Qlp + src + c * 8);
        }
    }
    flash_issue_kv(sb, 0, 0, b, kvh, tid, Qhp, Qlp);
    CP_COMMIT();
    if (iters > 1) {
        flash_issue_kv(sb, 1, 64, b, kvh, tid, Qhp, Qlp);
        CP_COMMIT();
        CP_WAIT1();
    } else {
        CP_WAIT0();
    }
    __syncthreads();

    uint32_t qh[4][4], ql[4][4];
    {
        uint32_t qa = sb + (uint32_t)((wid * 16 + (lane & 15)) * SKS
                                      + (lane >> 4) * 16);
#pragma unroll
        for (int t = 0; t < 4; t++) {
            ldsm4(qh[t], qa + t * 32);
            ldsm4(ql[t], qa + FL_QL + t * 32);
        }
    }

    float o[8][4];
#pragma unroll
    for (int j = 0; j < 8; j++)
#pragma unroll
        for (int q = 0; q < 4; q++) o[j][q] = 0.f;
    float mA = -1e30f, mB = -1e30f, lA = 0.f, lB = 0.f;

    const int qA = q0 + wid * 16 + (lane >> 2);
    const int qB = qA + 8;

    for (int it = 0; it < iters; it++) {
        const int s0 = it * 64;
        const uint32_t base = sb + FL_ST0 + (uint32_t)(it & 1) * FL_STAGE;

        float sc[8][4];
#pragma unroll
        for (int j = 0; j < 8; j++)
#pragma unroll
            for (int q = 0; q < 4; q++) sc[j][q] = 0.f;

        const uint32_t kb0 = (uint32_t)(((lane & 7) + ((lane >> 4) & 1) * 8) * SKS
                                        + ((lane >> 3) & 1) * 16);
#pragma unroll
        for (int t = 0; t < 4; t++) {
            uint32_t kh[4][4], kl[4][4];
#pragma unroll
            for (int p = 0; p < 4; p++) {
                uint32_t off = kb0 + (uint32_t)(p * 16 * SKS) + t * 32;
                ldsm4(kh[p], base + off);
                ldsm4(kl[p], base + 9216 + off);
            }
#pragma unroll
            for (int j = 0; j < 8; j++) {
                const uint32_t* bhp = &kh[j >> 1][(j & 1) * 2];
                const uint32_t* blp = &kl[j >> 1][(j & 1) * 2];
                mma_bf16(sc[j], qh[t], bhp);
                mma_bf16(sc[j], qh[t], blp);
                mma_bf16(sc[j], ql[t], bhp);
            }
        }

        // causal mask (raw scores; scale folded into exp arg)
#pragma unroll
        for (int j = 0; j < 8; j++) {
            int s = s0 + j * 8 + (lane & 3) * 2;
            sc[j][0] = (s     <= qA) ? sc[j][0] : -1e30f;
            sc[j][1] = (s + 1 <= qA) ? sc[j][1] : -1e30f;
            sc[j][2] = (s     <= qB) ? sc[j][2] : -1e30f;
            sc[j][3] = (s + 1 <= qB) ? sc[j][3] : -1e30f;
        }

        float tmA = -1e30f, tmB = -1e30f;
#pragma unroll
        for (int j = 0; j < 8; j++) {
            tmA = fmaxf(tmA, fmaxf(sc[j][0], sc[j][1]));
            tmB = fmaxf(tmB, fmaxf(sc[j][2], sc[j][3]));
        }
        tmA = fmaxf(tmA, __shfl_xor_sync(0xffffffffu, tmA, 1));
        tmA = fmaxf(tmA, __shfl_xor_sync(0xffffffffu, tmA, 2));
        tmB = fmaxf(tmB, __shfl_xor_sync(0xffffffffu, tmB, 1));
        tmB = fmaxf(tmB, __shfl_xor_sync(0xffffffffu, tmB, 2));
        float nmA = fmaxf(mA, tmA), nmB = fmaxf(mB, tmB);
        float aA = exp2f((mA - nmA) * SCL);
        float aB = exp2f((mB - nmB) * SCL);
        mA = nmA; mB = nmB;
        float nAs = nmA * SCL, nBs = nmB * SCL;

        float sumA = 0.f, sumB = 0.f;
#pragma unroll
        for (int j = 0; j < 8; j++) {
            sc[j][0] = exp2f(fmaf(sc[j][0], SCL, -nAs));
            sc[j][1] = exp2f(fmaf(sc[j][1], SCL, -nAs));
            sc[j][2] = exp2f(fmaf(sc[j][2], SCL, -nBs));
            sc[j][3] = exp2f(fmaf(sc[j][3], SCL, -nBs));
            sumA += sc[j][0] + sc[j][1];
            sumB += sc[j][2] + sc[j][3];
        }
        sumA += __shfl_xor_sync(0xffffffffu, sumA, 1);
        sumA += __shfl_xor_sync(0xffffffffu, sumA, 2);
        sumB += __shfl_xor_sync(0xffffffffu, sumB, 1);
        sumB += __shfl_xor_sync(0xffffffffu, sumB, 2);
        lA = lA * aA + sumA;
        lB = lB * aB + sumB;
#pragma unroll
        for (int j = 0; j < 8; j++) {
            o[j][0] *= aA; o[j][1] *= aA;
            o[j][2] *= aB; o[j][3] *= aB;
        }

        const uint32_t vb0 = (uint32_t)(((lane & 7) + ((lane >> 3) & 1) * 8) * SKS
                                        + ((lane >> 4) & 1) * 16);
#pragma unroll
        for (int t = 0; t < 4; t++) {
            uint32_t ah[4], al[4];
            ah[0] = pack_split(sc[2 * t][0],     sc[2 * t][1],     &al[0]);
            ah[1] = pack_split(sc[2 * t][2],     sc[2 * t][3],     &al[1]);
            ah[2] = pack_split(sc[2 * t + 1][0], sc[2 * t + 1][1], &al[2]);
            ah[3] = pack_split(sc[2 * t + 1][2], sc[2 * t + 1][3], &al[3]);
            uint32_t vh[4][4], vl[4][4];
#pragma unroll
            for (int p = 0; p < 4; p++) {
                uint32_t off = vb0 + (uint32_t)(t * 16 * SKS) + p * 32;
                ldsm4t(vh[p], base + 18432 + off);
                ldsm4t(vl[p], base + 27648 + off);
            }
#pragma unroll
            for (int j = 0; j < 8; j++) {
                const uint32_t* bhp = &vh[j >> 1][(j & 1) * 2];
                const uint32_t* blp = &vl[j >> 1][(j & 1) * 2];
                mma_bf16(o[j], ah, bhp);
                mma_bf16(o[j], ah, blp);
                mma_bf16(o[j], al, bhp);
            }
        }

        __syncthreads();
        if (it + 2 < iters) {
            flash_issue_kv(sb, it & 1, (it + 2) * 64, b, kvh, tid, Qhp, Qlp);
            CP_COMMIT();
        }
        if (it + 1 < iters) {
            if (it + 2 < iters) CP_WAIT1(); else CP_WAIT0();
            __syncthreads();
        }
    }

    float rA = 1.f / lA, rB = 1.f / lB;
    size_t tokA = (size_t)(b * TT + q0 + wid * 16 + (lane >> 2));
    size_t tokB = tokA + 8;
#pragma unroll
    for (int j = 0; j < 8; j++) {
        int col = hq * HDIM + j * 8 + (lane & 3) * 2;
        uint32_t l0, l1;
        uint32_t h0 = pack_split(o[j][0] * rA, o[j][1] * rA, &l0);
        uint32_t h1 = pack_split(o[j][2] * rB, o[j][3] * rB, &l1);
        size_t i0 = (tokA * CDIM + col) >> 1;
        size_t i1 = (tokB * CDIM + col) >> 1;
        Oh[i0] = h0; Ol[i0] = l0;
        Oh[i1] = h1; Ol[i1] = l1;
    }
}

// ===========================================================================
// add + LayerNorm
// ===========================================================================
template <bool SPLIT>
__global__ __launch_bounds__(256) void add_ln_kernel(
    const float* __restrict__ resid, const float* __restrict__ delta,
    const float* __restrict__ gamma, const float* __restrict__ beta,
    float* __restrict__ out, uint32_t* __restrict__ oh,
    uint32_t* __restrict__ ol)
{
    size_t row = blockIdx.x;
    int tid = threadIdx.x;

    float4 rv = reinterpret_cast<const float4*>(resid + row * CDIM)[tid];
    float4 dv = reinterpret_cast<const float4*>(delta + row * CDIM)[tid];
    float v0 = rv.x + dv.x, v1 = rv.y + dv.y, v2 = rv.z + dv.z, v3 = rv.w + dv.w;

    __shared__ float rs[256], rss[256];
    rs[tid]  = v0 + v1 + v2 + v3;
    rss[tid] = v0 * v0 + v1 * v1 + v2 * v2 + v3 * v3;
    __syncthreads();
    for (int s = 128; s > 0; s >>= 1) {
        if (tid < s) { rs[tid] += rs[tid + s]; rss[tid] += rss[tid + s]; }
        __syncthreads();
    }
    float mu  = rs[0]  * (1.f / CDIM);
    float var = rss[0] * (1.f / CDIM) - mu * mu;
    float inv = rsqrtf(var + 1e-5f);

    float4 g  = reinterpret_cast<const float4*>(gamma)[tid];
    float4 bb = reinterpret_cast<const float4*>(beta)[tid];
    float4 ov;
    ov.x = (v0 - mu) * inv * g.x + bb.x;
    ov.y = (v1 - mu) * inv * g.y + bb.y;
    ov.z = (v2 - mu) * inv * g.z + bb.z;
    ov.w = (v3 - mu) * inv * g.w + bb.w;
    reinterpret_cast<float4*>(out + row * CDIM)[tid] = ov;
    if (SPLIT) {
        uint32_t l0, l1;
        uint32_t h0 = pack_split(ov.x, ov.y, &l0);
        uint32_t h1 = pack_split(ov.z, ov.w, &l1);
        size_t i0 = (row * CDIM) / 2 + tid * 2;
        oh[i0] = h0; ol[i0] = l0;
        oh[i0 + 1] = h1; ol[i0 + 1] = l1;
    }
}

// ===========================================================================
extern "C" void kernel_launch(void* const* d_in, const int* in_sizes, int n_in,
                              void* d_out, int out_size)
{
    const float* x    = (const float*)d_in[0];
    const float* ipw  = (const float*)d_in[1];
    const float* ipb  = (const float*)d_in[2];
    const float* ow   = (const float*)d_in[3];
    const float* ob   = (const float*)d_in[4];
    const float* w1   = (const float*)d_in[5];
    const float* b1   = (const float*)d_in[6];
    const float* w2   = (const float*)d_in[7];
    const float* b2   = (const float*)d_in[8];
    const float* ln1g = (const float*)d_in[9];
    const float* ln1b = (const float*)d_in[10];
    const float* ln2g = (const float*)d_in[11];
    const float* ln2b = (const float*)d_in[12];
    float* out = (float*)d_out;

    float *px, *py;
    uint16_t *pxh, *pxl, *pqh, *pql, *poh, *pol, *pfh, *pfl;
    uint16_t *pwih, *pwil, *pwoh, *pwol, *pw1h, *pw1l, *pw2h, *pw2l;
    cudaGetSymbolAddress((void**)&px,   g_x);
    cudaGetSymbolAddress((void**)&py,   g_y);
    cudaGetSymbolAddress((void**)&pxh,  g_xh);
    cudaGetSymbolAddress((void**)&pxl,  g_xl);
    cudaGetSymbolAddress((void**)&pqh,  g_qh);
    cudaGetSymbolAddress((void**)&pql,  g_ql);
    cudaGetSymbolAddress((void**)&poh,  g_oh);
    cudaGetSymbolAddress((void**)&pol,  g_ol);
    cudaGetSymbolAddress((void**)&pfh,  g_fh);
    cudaGetSymbolAddress((void**)&pfl,  g_fl);
    cudaGetSymbolAddress((void**)&pwih, g_wih);
    cudaGetSymbolAddress((void**)&pwil, g_wil);
    cudaGetSymbolAddress((void**)&pwoh, g_woh);
    cudaGetSymbolAddress((void**)&pwol, g_wol);
    cudaGetSymbolAddress((void**)&pw1h, g_w1h);
    cudaGetSymbolAddress((void**)&pw1l, g_w1l);
    cudaGetSymbolAddress((void**)&pw2h, g_w2h);
    cudaGetSymbolAddress((void**)&pw2l, g_w2l);

    cudaFuncSetAttribute(gemm_mma_kernel<false, false>,
                         cudaFuncAttributeMaxDynamicSharedMemorySize, G_SMEM);
    cudaFuncSetAttribute(gemm_mma_kernel<false, true>,
                         cudaFuncAttributeMaxDynamicSharedMemorySize, G_SMEM);
    cudaFuncSetAttribute(gemm_mma_kernel<true, true>,
                         cudaFuncAttributeMaxDynamicSharedMemorySize, G_SMEM);
    cudaFuncSetAttribute(flash_kernel,
                         cudaFuncAttributeMaxDynamicSharedMemorySize, FL_SMEM);

    // 1: copy+split input
    copy_in_kernel<<<NTOK * CDIM / 1024, 256>>>(
        (const float4*)x, (float4*)px, (uint2*)pxh, (uint2*)pxl);
    // 2: split in_proj + out weights
    split2_kernel<<<(NLAYER * QKVD * CDIM + NLAYER * CDIM * CDIM) / 1024, 256>>>(
        (const float4*)ipw, NLAYER * QKVD * CDIM / 1024,
        (uint2*)pwih, (uint2*)pwil,
        (const float4*)ow, (uint2*)pwoh, (uint2*)pwol);
    // 3: split w1 + w2 weights
    split2_kernel<<<2 * NLAYER * FFD * CDIM / 1024, 256>>>(
        (const float4*)w1, NLAYER * FFD * CDIM / 1024,
        (uint2*)pw1h, (uint2*)pw1l,
        (const float4*)w2, (uint2*)pw2h, (uint2*)pw2l);

    for (int l = 0; l < NLAYER; l++) {
        gemm_mma_kernel<false, true><<<dim3(QKVD / 128, NTOK / 128), 256, G_SMEM>>>(
            pxh, pxl,
            pwih + (size_t)l * QKVD * CDIM, pwil + (size_t)l * QKVD * CDIM,
            ipb + (size_t)l * QKVD, nullptr, (uint32_t*)pqh, (uint32_t*)pql,
            CDIM, QKVD);

        flash_kernel<<<dim3(TT / 128, NBH), 256, FL_SMEM>>>(
            pqh, pql, (uint32_t*)poh, (uint32_t*)pol);

        gemm_mma_kernel<false, false><<<dim3(CDIM / 128, NTOK / 128), 256, G_SMEM>>>(
            poh, pol,
            pwoh + (size_t)l * CDIM * CDIM, pwol + (size_t)l * CDIM * CDIM,
            ob + (size_t)l * CDIM, py, nullptr, nullptr, CDIM, CDIM);

        add_ln_kernel<true><<<NTOK, 256>>>(px, py,
            ln1g + (size_t)l * CDIM, ln1b + (size_t)l * CDIM, px,
            (uint32_t*)pxh, (uint32_t*)pxl);

        gemm_mma_kernel<true, true><<<dim3(FFD / 128, NTOK / 128), 256, G_SMEM>>>(
            pxh, pxl,
            pw1h + (size_t)l * FFD * CDIM, pw1l + (size_t)l * FFD * CDIM,
            b1 + (size_t)l * FFD, nullptr, (uint32_t*)pfh, (uint32_t*)pfl,
            CDIM, FFD);

        gemm_mma_kernel<false, false><<<dim3(CDIM / 128, NTOK / 128), 256, G_SMEM>>>(
            pfh, pfl,
            pw2h + (size_t)l * CDIM * FFD, pw2l + (size_t)l * CDIM * FFD,
            b2 + (size_t)l * CDIM, py, nullptr, nullptr, FFD, CDIM);

        if (l == NLAYER - 1) {
            add_ln_kernel<false><<<NTOK, 256>>>(px, py,
                ln2g + (size_t)l * CDIM, ln2b + (size_t)l * CDIM, out,
                nullptr, nullptr);
        } else {
            add_ln_kernel<true><<<NTOK, 256>>>(px, py,
                ln2g + (size_t)l * CDIM, ln2b + (size_t)l * CDIM, px,
                (uint32_t*)pxh, (uint32_t*)pxl);
        }
    }
}

// round 13
// speedup vs baseline: 1.0717x; 1.0717x over previous
#include <cuda_runtime.h>
#include <cstdint>

// ---------------------------------------------------------------------------
// Transformer encoder: split-bf16 mma.sync GEMMs (R5 config + 2 CTAs/SM via
// launch_bounds) + fused flash attention with LPT CTA ordering.
// B=4, T=1024, C=1024, H=16, HD=64, FF=4096, L=4
// ---------------------------------------------------------------------------

#define NTOK   4096
#define CDIM   1024
#define QKVD   1536
#define KVOFF  1024
#define VOFF   1280
#define FFD    4096
#define TT     1024
#define NBH    64
#define HDIM   64
#define NLAYER 4

// ---- fp32 scratch ----
__device__ float g_x[NTOK * CDIM];
__device__ float g_y[NTOK * CDIM];

// ---- split-bf16 activation planes ----
__device__ uint16_t g_xh[NTOK * CDIM];
__device__ uint16_t g_xl[NTOK * CDIM];
__device__ uint16_t g_qh[NTOK * QKVD];
__device__ uint16_t g_ql[NTOK * QKVD];
__device__ uint16_t g_oh[NTOK * CDIM];
__device__ uint16_t g_ol[NTOK * CDIM];
__device__ uint16_t g_fh[NTOK * FFD];
__device__ uint16_t g_fl[NTOK * FFD];

// ---- split-bf16 weight planes ----
__device__ uint16_t g_wih[NLAYER * QKVD * CDIM];
__device__ uint16_t g_wil[NLAYER * QKVD * CDIM];
__device__ uint16_t g_woh[NLAYER * CDIM * CDIM];
__device__ uint16_t g_wol[NLAYER * CDIM * CDIM];
__device__ uint16_t g_w1h[NLAYER * FFD * CDIM];
__device__ uint16_t g_w1l[NLAYER * FFD * CDIM];
__device__ uint16_t g_w2h[NLAYER * CDIM * FFD];
__device__ uint16_t g_w2l[NLAYER * CDIM * FFD];

// ===========================================================================
// helpers
// ===========================================================================
__device__ __forceinline__ uint32_t smem_u32(const void* p) {
    uint32_t a;
    asm("{ .reg .u64 t; cvta.to.shared.u64 t, %1; cvt.u32.u64 %0, t; }"
        : "=r"(a) : "l"(p));
    return a;
}
__device__ __forceinline__ uint32_t f2bf_rn(float x) {
    uint32_t u = __float_as_uint(x);
    return (u + 0x7FFFu + ((u >> 16) & 1u)) >> 16;
}
__device__ __forceinline__ float bf2f(uint32_t h) {
    return __uint_as_float(h << 16);
}
__device__ __forceinline__ uint32_t pack_split(float a, float b, uint32_t* lo) {
    uint32_t ha = f2bf_rn(a), hb = f2bf_rn(b);
    *lo = f2bf_rn(a - bf2f(ha)) | (f2bf_rn(b - bf2f(hb)) << 16);
    return ha | (hb << 16);
}

#define CP16(dst, src) \
    asm volatile("cp.async.cg.shared.global [%0], [%1], 16;" \
                 :: "r"(dst), "l"(src))
#define CP_COMMIT() asm volatile("cp.async.commit_group;" ::: "memory")
#define CP_WAIT0()  asm volatile("cp.async.wait_group 0;" ::: "memory")
#define CP_WAIT1()  asm volatile("cp.async.wait_group 1;" ::: "memory")

__device__ __forceinline__ void ldsm4(uint32_t* r, uint32_t addr) {
    asm volatile("ldmatrix.sync.aligned.m8n8.x4.shared.b16 {%0,%1,%2,%3}, [%4];"
                 : "=r"(r[0]), "=r"(r[1]), "=r"(r[2]), "=r"(r[3]) : "r"(addr));
}
__device__ __forceinline__ void ldsm4t(uint32_t* r, uint32_t addr) {
    asm volatile("ldmatrix.sync.aligned.m8n8.x4.trans.shared.b16 {%0,%1,%2,%3}, [%4];"
                 : "=r"(r[0]), "=r"(r[1]), "=r"(r[2]), "=r"(r[3]) : "r"(addr));
}
__device__ __forceinline__ void mma_bf16(float* c, const uint32_t* a,
                                         const uint32_t* b) {
    asm volatile(
        "mma.sync.aligned.m16n8k16.row.col.f32.bf16.bf16.f32 "
        "{%0,%1,%2,%3}, {%4,%5,%6,%7}, {%8,%9}, {%0,%1,%2,%3};"
        : "+f"(c[0]), "+f"(c[1]), "+f"(c[2]), "+f"(c[3])
        : "r"(a[0]), "r"(a[1]), "r"(a[2]), "r"(a[3]), "r"(b[0]), "r"(b[1]));
}

// ===========================================================================
// split kernels
// ===========================================================================
__global__ __launch_bounds__(256) void split2_kernel(
    const float4* __restrict__ s1, int n1blocks,
    uint2* __restrict__ h1, uint2* __restrict__ l1,
    const float4* __restrict__ s2,
    uint2* __restrict__ h2, uint2* __restrict__ l2)
{
    int blk = blockIdx.x;
    const float4* src; uint2 *hi, *lo; size_t i;
    if (blk < n1blocks) {
        i = (size_t)blk * 256 + threadIdx.x; src = s1; hi = h1; lo = l1;
    } else {
        i = (size_t)(blk - n1blocks) * 256 + threadIdx.x;
        src = s2; hi = h2; lo = l2;
    }
    float4 v = src[i];
    uint32_t l0, l1r;
    uint32_t h0 = pack_split(v.x, v.y, &l0);
    uint32_t h1r = pack_split(v.z, v.w, &l1r);
    hi[i] = make_uint2(h0, h1r);
    lo[i] = make_uint2(l0, l1r);
}

__global__ __launch_bounds__(256) void copy_in_kernel(
    const float4* __restrict__ src, float4* __restrict__ dst,
    uint2* __restrict__ hi, uint2* __restrict__ lo)
{
    size_t i = (size_t)blockIdx.x * 256 + threadIdx.x;
    float4 v = src[i];
    dst[i] = v;
    uint32_t l0, l1;
    uint32_t h0 = pack_split(v.x, v.y, &l0);
    uint32_t h1 = pack_split(v.z, v.w, &l1);
    hi[i] = make_uint2(h0, h1);
    lo[i] = make_uint2(l0, l1);
}

// ===========================================================================
// mma.sync GEMM: CTA 128x128, warp tile 64x32, BK=32, 2-stage, split-bf16 x3.
// __launch_bounds__(256, 2) caps regs at 128 so 2 CTAs co-reside per SM
// (profile showed regs=130 -> 1 CTA/SM, occ 12.4%, tensor pipe only 43%).
// ===========================================================================
#define G_STAGE 40960
#define G_SMEM  (2 * G_STAGE)

__device__ __forceinline__ void gemm_issue(
    uint32_t sb, int buf, int kb,
    const uint16_t* Ah, const uint16_t* Al,
    const uint16_t* Wh, const uint16_t* Wl,
    int row0, int col0, int K, int tid)
{
    uint32_t dst = sb + (uint32_t)buf * G_STAGE;
    int ch = tid & 3;
    size_t kbase = (size_t)kb * 32 + ch * 8;
#pragma unroll
    for (int i = 0; i < 2; i++) {
        int r = (tid >> 2) + i * 64;
        uint32_t so = (uint32_t)(r * 80 + ch * 16);
        CP16(dst + so,         Ah + (size_t)(row0 + r) * K + kbase);
        CP16(dst + 10240 + so, Al + (size_t)(row0 + r) * K + kbase);
        CP16(dst + 20480 + so, Wh + (size_t)(col0 + r) * K + kbase);
        CP16(dst + 30720 + so, Wl + (size_t)(col0 + r) * K + kbase);
    }
}

template <bool RELU, bool SPLIT>
__global__ __launch_bounds__(256, 2) void gemm_mma_kernel(
    const uint16_t* __restrict__ Ah, const uint16_t* __restrict__ Al,
    const uint16_t* __restrict__ Wh, const uint16_t* __restrict__ Wl,
    const float* __restrict__ bias, float* __restrict__ outf,
    uint32_t* __restrict__ outh, uint32_t* __restrict__ outl,
    int K, int N)
{
    extern __shared__ char sm[];
    const uint32_t sb = smem_u32(sm);
    const int tid = threadIdx.x, lane = tid & 31, wid = tid >> 5;
    const int row0 = blockIdx.y << 7, col0 = blockIdx.x << 7;
    const int m0 = (wid >> 2) << 6;
    const int n0 = (wid & 3) << 5;

    const uint32_t aoff = (uint32_t)((m0 + (lane & 15)) * 80 + (lane >> 4) * 16);
    const uint32_t boff = (uint32_t)((n0 + (lane & 7) + ((lane >> 4) & 1) * 8) * 80
                                     + ((lane >> 3) & 1) * 16);

    float acc[4][4][4];
#pragma unroll
    for (int mi = 0; mi < 4; mi++)
#pragma unroll
        for (int ni = 0; ni < 4; ni++)
#pragma unroll
            for (int q = 0; q < 4; q++) acc[mi][ni][q] = 0.f;

    const int nkb = K >> 5;
    gemm_issue(sb, 0, 0, Ah, Al, Wh, Wl, row0, col0, K, tid);
    CP_COMMIT();

    for (int kb = 0; kb < nkb; kb++) {
        CP_WAIT0();
        __syncthreads();
        if (kb + 1 < nkb) {
            gemm_issue(sb, (kb + 1) & 1, kb + 1, Ah, Al, Wh, Wl,
                       row0, col0, K, tid);
            CP_COMMIT();
        }
        const uint32_t base = sb + (uint32_t)(kb & 1) * G_STAGE;
#pragma unroll
        for (int ks = 0; ks < 2; ks++) {
            uint32_t fah[4][4], fal[4][4], fbh[2][4], fbl[2][4];
#pragma unroll
            for (int mi = 0; mi < 4; mi++) {
                uint32_t off = aoff + mi * 1280 + ks * 32;
                ldsm4(fah[mi], base + off);
                ldsm4(fal[mi], base + 10240 + off);
            }
#pragma unroll
            for (int nj = 0; nj < 2; nj++) {
                uint32_t off = boff + nj * 1280 + ks * 32;
                ldsm4(fbh[nj], base + 20480 + off);
                ldsm4(fbl[nj], base + 30720 + off);
            }
#pragma unroll
            for (int mi = 0; mi < 4; mi++) {
#pragma unroll
                for (int ni = 0; ni < 4; ni++) {
                    const uint32_t* bh = &fbh[ni >> 1][(ni & 1) * 2];
                    const uint32_t* bl = &fbl[ni >> 1][(ni & 1) * 2];
                    mma_bf16(acc[mi][ni], fah[mi], bh);
                    mma_bf16(acc[mi][ni], fah[mi], bl);
                    mma_bf16(acc[mi][ni], fal[mi], bh);
                }
            }
        }
        __syncthreads();
    }

#pragma unroll
    for (int mi = 0; mi < 4; mi++) {
        int row = row0 + m0 + mi * 16 + (lane >> 2);
#pragma unroll
        for (int ni = 0; ni < 4; ni++) {
            int col = col0 + n0 + ni * 8 + (lane & 3) * 2;
            float b0 = __ldg(&bias[col]), b1 = __ldg(&bias[col + 1]);
            float v00 = acc[mi][ni][0] + b0, v01 = acc[mi][ni][1] + b1;
            float v10 = acc[mi][ni][2] + b0, v11 = acc[mi][ni][3] + b1;
            if (RELU) {
                v00 = fmaxf(v00, 0.f); v01 = fmaxf(v01, 0.f);
                v10 = fmaxf(v10, 0.f); v11 = fmaxf(v11, 0.f);
            }
            if (SPLIT) {
                uint32_t l0, l1;
                uint32_t h0 = pack_split(v00, v01, &l0);
                uint32_t h1 = pack_split(v10, v11, &l1);
                size_t i0 = ((size_t)row * N + col) >> 1;
                size_t i1 = ((size_t)(row + 8) * N + col) >> 1;
                outh[i0] = h0; outl[i0] = l0;
                outh[i1] = h1; outl[i1] = l1;
            } else {
                *reinterpret_cast<float2*>(&outf[(size_t)row * N + col]) =
                    make_float2(v00, v01);
                *reinterpret_cast<float2*>(&outf[(size_t)(row + 8) * N + col]) =
                    make_float2(v10, v11);
            }
        }
    }
}

// ===========================================================================
// fused flash attention, LPT ordering
// ===========================================================================
#define SKS      144
#define FL_QL    18432
#define FL_ST0   36864
#define FL_STAGE 36864
#define FL_SMEM  (FL_ST0 + 2 * FL_STAGE)
#define SCL      0.1803368801111204f   // 0.125 * log2(e)

__device__ __forceinline__ void flash_issue_kv(
    uint32_t sb, int buf, int s0, int b, int kvh, int tid,
    const uint16_t* Qhp, const uint16_t* Qlp)
{
    uint32_t dst = sb + FL_ST0 + (uint32_t)buf * FL_STAGE;
    int r = tid >> 2;
    int c0 = (tid & 3) * 2;
    size_t rowoff = (size_t)(b * TT + s0 + r) * QKVD;
    const uint16_t* kh = Qhp + rowoff + KVOFF + kvh * HDIM;
    const uint16_t* kl = Qlp + rowoff + KVOFF + kvh * HDIM;
    const uint16_t* vh = Qhp + rowoff + VOFF + kvh * HDIM;
    const uint16_t* vl = Qlp + rowoff + VOFF + kvh * HDIM;
    uint32_t so = (uint32_t)(r * SKS + c0 * 16);
#pragma unroll
    for (int c = 0; c < 2; c++) {
        CP16(dst + so + c * 16,         kh + (c0 + c) * 8);
        CP16(dst + 9216 + so + c * 16,  kl + (c0 + c) * 8);
        CP16(dst + 18432 + so + c * 16, vh + (c0 + c) * 8);
        CP16(dst + 27648 + so + c * 16, vl + (c0 + c) * 8);
    }
}

__global__ __launch_bounds__(256) void flash_kernel(
    const uint16_t* __restrict__ Qhp, const uint16_t* __restrict__ Qlp,
    uint32_t* __restrict__ Oh, uint32_t* __restrict__ Ol)
{
    extern __shared__ char sm[];
    const uint32_t sb = smem_u32(sm);
    const int tid = threadIdx.x, lane = tid & 31, wid = tid >> 5;
    const int bh = blockIdx.y, b = bh >> 4, hq = bh & 15, kvh = hq & 3;
    const int xr = (int)gridDim.x - 1 - (int)blockIdx.x;
    const int q0 = xr * 128;
    const int iters = 2 * (xr + 1);

    {
        int r = tid >> 1;
        int cb = (tid & 1) * 4;
        size_t src = (size_t)(b * TT + q0 + r) * QKVD + hq * HDIM + cb * 8;
        uint32_t d0 = sb + r * SKS + cb * 16;
#pragma unroll
        for (int c = 0; c < 4; c++) {
            CP16(d0 + c * 16,          Qhp + src + c * 8);
            CP16(d0 + FL_QL + c * 16,  Qlp + src + c * 8);
        }
    }
    flash_issue_kv(sb, 0, 0, b, kvh, tid, Qhp, Qlp);
    CP_COMMIT();
    if (iters > 1) {
        flash_issue_kv(sb, 1, 64, b, kvh, tid, Qhp, Qlp);
        CP_COMMIT();
        CP_WAIT1();
    } else {
        CP_WAIT0();
    }
    __syncthreads();

    uint32_t qh[4][4], ql[4][4];
    {
        uint32_t qa = sb + (uint32_t)((wid * 16 + (lane & 15)) * SKS
                                      + (lane >> 4) * 16);
#pragma unroll
        for (int t = 0; t < 4; t++) {
            ldsm4(qh[t], qa + t * 32);
            ldsm4(ql[t], qa + FL_QL + t * 32);
        }
    }

    float o[8][4];
#pragma unroll
    for (int j = 0; j < 8; j++)
#pragma unroll
        for (int q = 0; q < 4; q++) o[j][q] = 0.f;
    float mA = -1e30f, mB = -1e30f, lA = 0.f, lB = 0.f;

    const int qA = q0 + wid * 16 + (lane >> 2);
    const int qB = qA + 8;

    for (int it = 0; it < iters; it++) {
        const int s0 = it * 64;
        const uint32_t base = sb + FL_ST0 + (uint32_t)(it & 1) * FL_STAGE;

        float sc[8][4];
#pragma unroll
        for (int j = 0; j < 8; j++)
#pragma unroll
            for (int q = 0; q < 4; q++) sc[j][q] = 0.f;

        const uint32_t kb0 = (uint32_t)(((lane & 7) + ((lane >> 4) & 1) * 8) * SKS
                                        + ((lane >> 3) & 1) * 16);
#pragma unroll
        for (int t = 0; t < 4; t++) {
            uint32_t kh[4][4], kl[4][4];
#pragma unroll
            for (int p = 0; p < 4; p++) {
                uint32_t off = kb0 + (uint32_t)(p * 16 * SKS) + t * 32;
                ldsm4(kh[p], base + off);
                ldsm4(kl[p], base + 9216 + off);
            }
#pragma unroll
            for (int j = 0; j < 8; j++) {
                const uint32_t* bhp = &kh[j >> 1][(j & 1) * 2];
                const uint32_t* blp = &kl[j >> 1][(j & 1) * 2];
                mma_bf16(sc[j], qh[t], bhp);
                mma_bf16(sc[j], qh[t], blp);
                mma_bf16(sc[j], ql[t], bhp);
            }
        }

#pragma unroll
        for (int j = 0; j < 8; j++) {
            int s = s0 + j * 8 + (lane & 3) * 2;
            sc[j][0] = (s     <= qA) ? sc[j][0] : -1e30f;
            sc[j][1] = (s + 1 <= qA) ? sc[j][1] : -1e30f;
            sc[j][2] = (s     <= qB) ? sc[j][2] : -1e30f;
            sc[j][3] = (s + 1 <= qB) ? sc[j][3] : -1e30f;
        }

        float tmA = -1e30f, tmB = -1e30f;
#pragma unroll
        for (int j = 0; j < 8; j++) {
            tmA = fmaxf(tmA, fmaxf(sc[j][0], sc[j][1]));
            tmB = fmaxf(tmB, fmaxf(sc[j][2], sc[j][3]));
        }
        tmA = fmaxf(tmA, __shfl_xor_sync(0xffffffffu, tmA, 1));
        tmA = fmaxf(tmA, __shfl_xor_sync(0xffffffffu, tmA, 2));
        tmB = fmaxf(tmB, __shfl_xor_sync(0xffffffffu, tmB, 1));
        tmB = fmaxf(tmB, __shfl_xor_sync(0xffffffffu, tmB, 2));
        float nmA = fmaxf(mA, tmA), nmB = fmaxf(mB, tmB);
        float aA = exp2f((mA - nmA) * SCL);
        float aB = exp2f((mB - nmB) * SCL);
        mA = nmA; mB = nmB;
        float nAs = nmA * SCL, nBs = nmB * SCL;

        float sumA = 0.f, sumB = 0.f;
#pragma unroll
        for (int j = 0; j < 8; j++) {
            sc[j][0] = exp2f(fmaf(sc[j][0], SCL, -nAs));
            sc[j][1] = exp2f(fmaf(sc[j][1], SCL, -nAs));
            sc[j][2] = exp2f(fmaf(sc[j][2], SCL, -nBs));
            sc[j][3] = exp2f(fmaf(sc[j][3], SCL, -nBs));
            sumA += sc[j][0] + sc[j][1];
            sumB += sc[j][2] + sc[j][3];
        }
        sumA += __shfl_xor_sync(0xffffffffu, sumA, 1);
        sumA += __shfl_xor_sync(0xffffffffu, sumA, 2);
        sumB += __shfl_xor_sync(0xffffffffu, sumB, 1);
        sumB += __shfl_xor_sync(0xffffffffu, sumB, 2);
        lA = lA * aA + sumA;
        lB = lB * aB + sumB;
#pragma unroll
        for (int j = 0; j < 8; j++) {
            o[j][0] *= aA; o[j][1] *= aA;
            o[j][2] *= aB; o[j][3] *= aB;
        }

        const uint32_t vb0 = (uint32_t)(((lane & 7) + ((lane >> 3) & 1) * 8) * SKS
                                        + ((lane >> 4) & 1) * 16);
#pragma unroll
        for (int t = 0; t < 4; t++) {
            uint32_t ah[4], al[4];
            ah[0] = pack_split(sc[2 * t][0],     sc[2 * t][1],     &al[0]);
            ah[1] = pack_split(sc[2 * t][2],     sc[2 * t][3],     &al[1]);
            ah[2] = pack_split(sc[2 * t + 1][0], sc[2 * t + 1][1], &al[2]);
            ah[3] = pack_split(sc[2 * t + 1][2], sc[2 * t + 1][3], &al[3]);
            uint32_t vh[4][4], vl[4][4];
#pragma unroll
            for (int p = 0; p < 4; p++) {
                uint32_t off = vb0 + (uint32_t)(t * 16 * SKS) + p * 32;
                ldsm4t(vh[p], base + 18432 + off);
                ldsm4t(vl[p], base + 27648 + off);
            }
#pragma unroll
            for (int j = 0; j < 8; j++) {
                const uint32_t* bhp = &vh[j >> 1][(j & 1) * 2];
                const uint32_t* blp = &vl[j >> 1][(j & 1) * 2];
                mma_bf16(o[j], ah, bhp);
                mma_bf16(o[j], ah, blp);
                mma_bf16(o[j], al, bhp);
            }
        }

        __syncthreads();
        if (it + 2 < iters) {
            flash_issue_kv(sb, it & 1, (it + 2) * 64, b, kvh, tid, Qhp, Qlp);
            CP_COMMIT();
        }
        if (it + 1 < iters) {
            if (it + 2 < iters) CP_WAIT1(); else CP_WAIT0();
            __syncthreads();
        }
    }

    float rA = 1.f / lA, rB = 1.f / lB;
    size_t tokA = (size_t)(b * TT + q0 + wid * 16 + (lane >> 2));
    size_t tokB = tokA + 8;
#pragma unroll
    for (int j = 0; j < 8; j++) {
        int col = hq * HDIM + j * 8 + (lane & 3) * 2;
        uint32_t l0, l1;
        uint32_t h0 = pack_split(o[j][0] * rA, o[j][1] * rA, &l0);
        uint32_t h1 = pack_split(o[j][2] * rB, o[j][3] * rB, &l1);
        size_t i0 = (tokA * CDIM + col) >> 1;
        size_t i1 = (tokB * CDIM + col) >> 1;
        Oh[i0] = h0; Ol[i0] = l0;
        Oh[i1] = h1; Ol[i1] = l1;
    }
}

// ===========================================================================
// add + LayerNorm
// ===========================================================================
template <bool SPLIT>
__global__ __launch_bounds__(256) void add_ln_kernel(
    const float* __restrict__ resid, const float* __restrict__ delta,
    const float* __restrict__ gamma, const float* __restrict__ beta,
    float* __restrict__ out, uint32_t* __restrict__ oh,
    uint32_t* __restrict__ ol)
{
    size_t row = blockIdx.x;
    int tid = threadIdx.x;

    float4 rv = reinterpret_cast<const float4*>(resid + row * CDIM)[tid];
    float4 dv = reinterpret_cast<const float4*>(delta + row * CDIM)[tid];
    float v0 = rv.x + dv.x, v1 = rv.y + dv.y, v2 = rv.z + dv.z, v3 = rv.w + dv.w;

    __shared__ float rs[256], rss[256];
    rs[tid]  = v0 + v1 + v2 + v3;
    rss[tid] = v0 * v0 + v1 * v1 + v2 * v2 + v3 * v3;
    __syncthreads();
    for (int s = 128; s > 0; s >>= 1) {
        if (tid < s) { rs[tid] += rs[tid + s]; rss[tid] += rss[tid + s]; }
        __syncthreads();
    }
    float mu  = rs[0]  * (1.f / CDIM);
    float var = rss[0] * (1.f / CDIM) - mu * mu;
    float inv = rsqrtf(var + 1e-5f);

    float4 g  = reinterpret_cast<const float4*>(gamma)[tid];
    float4 bb = reinterpret_cast<const float4*>(beta)[tid];
    float4 ov;
    ov.x = (v0 - mu) * inv * g.x + bb.x;
    ov.y = (v1 - mu) * inv * g.y + bb.y;
    ov.z = (v2 - mu) * inv * g.z + bb.z;
    ov.w = (v3 - mu) * inv * g.w + bb.w;
    reinterpret_cast<float4*>(out + row * CDIM)[tid] = ov;
    if (SPLIT) {
        uint32_t l0, l1;
        uint32_t h0 = pack_split(ov.x, ov.y, &l0);
        uint32_t h1 = pack_split(ov.z, ov.w, &l1);
        size_t i0 = (row * CDIM) / 2 + tid * 2;
        oh[i0] = h0; ol[i0] = l0;
        oh[i0 + 1] = h1; ol[i0 + 1] = l1;
    }
}

// ===========================================================================
extern "C" void kernel_launch(void* const* d_in, const int* in_sizes, int n_in,
                              void* d_out, int out_size)
{
    const float* x    = (const float*)d_in[0];
    const float* ipw  = (const float*)d_in[1];
    const float* ipb  = (const float*)d_in[2];
    const float* ow   = (const float*)d_in[3];
    const float* ob   = (const float*)d_in[4];
    const float* w1   = (const float*)d_in[5];
    const float* b1   = (const float*)d_in[6];
    const float* w2   = (const float*)d_in[7];
    const float* b2   = (const float*)d_in[8];
    const float* ln1g = (const float*)d_in[9];
    const float* ln1b = (const float*)d_in[10];
    const float* ln2g = (const float*)d_in[11];
    const float* ln2b = (const float*)d_in[12];
    float* out = (float*)d_out;

    float *px, *py;
    uint16_t *pxh, *pxl, *pqh, *pql, *poh, *pol, *pfh, *pfl;
    uint16_t *pwih, *pwil, *pwoh, *pwol, *pw1h, *pw1l, *pw2h, *pw2l;
    cudaGetSymbolAddress((void**)&px,   g_x);
    cudaGetSymbolAddress((void**)&py,   g_y);
    cudaGetSymbolAddress((void**)&pxh,  g_xh);
    cudaGetSymbolAddress((void**)&pxl,  g_xl);
    cudaGetSymbolAddress((void**)&pqh,  g_qh);
    cudaGetSymbolAddress((void**)&pql,  g_ql);
    cudaGetSymbolAddress((void**)&poh,  g_oh);
    cudaGetSymbolAddress((void**)&pol,  g_ol);
    cudaGetSymbolAddress((void**)&pfh,  g_fh);
    cudaGetSymbolAddress((void**)&pfl,  g_fl);
    cudaGetSymbolAddress((void**)&pwih, g_wih);
    cudaGetSymbolAddress((void**)&pwil, g_wil);
    cudaGetSymbolAddress((void**)&pwoh, g_woh);
    cudaGetSymbolAddress((void**)&pwol, g_wol);
    cudaGetSymbolAddress((void**)&pw1h, g_w1h);
    cudaGetSymbolAddress((void**)&pw1l, g_w1l);
    cudaGetSymbolAddress((void**)&pw2h, g_w2h);
    cudaGetSymbolAddress((void**)&pw2l, g_w2l);

    cudaFuncSetAttribute(gemm_mma_kernel<false, false>,
                         cudaFuncAttributeMaxDynamicSharedMemorySize, G_SMEM);
    cudaFuncSetAttribute(gemm_mma_kernel<false, true>,
                         cudaFuncAttributeMaxDynamicSharedMemorySize, G_SMEM);
    cudaFuncSetAttribute(gemm_mma_kernel<true, true>,
                         cudaFuncAttributeMaxDynamicSharedMemorySize, G_SMEM);
    cudaFuncSetAttribute(flash_kernel,
                         cudaFuncAttributeMaxDynamicSharedMemorySize, FL_SMEM);

    copy_in_kernel<<<NTOK * CDIM / 1024, 256>>>(
        (const float4*)x, (float4*)px, (uint2*)pxh, (uint2*)pxl);
    split2_kernel<<<(NLAYER * QKVD * CDIM + NLAYER * CDIM * CDIM) / 1024, 256>>>(
        (const float4*)ipw, NLAYER * QKVD * CDIM / 1024,
        (uint2*)pwih, (uint2*)pwil,
        (const float4*)ow, (uint2*)pwoh, (uint2*)pwol);
    split2_kernel<<<2 * NLAYER * FFD * CDIM / 1024, 256>>>(
        (const float4*)w1, NLAYER * FFD * CDIM / 1024,
        (uint2*)pw1h, (uint2*)pw1l,
        (const float4*)w2, (uint2*)pw2h, (uint2*)pw2l);

    for (int l = 0; l < NLAYER; l++) {
        gemm_mma_kernel<false, true><<<dim3(QKVD / 128, NTOK / 128), 256, G_SMEM>>>(
            pxh, pxl,
            pwih + (size_t)l * QKVD * CDIM, pwil + (size_t)l * QKVD * CDIM,
            ipb + (size_t)l * QKVD, nullptr, (uint32_t*)pqh, (uint32_t*)pql,
            CDIM, QKVD);

        flash_kernel<<<dim3(TT / 128, NBH), 256, FL_SMEM>>>(
            pqh, pql, (uint32_t*)poh, (uint32_t*)pol);

        gemm_mma_kernel<false, false><<<dim3(CDIM / 128, NTOK / 128), 256, G_SMEM>>>(
            poh, pol,
            pwoh + (size_t)l * CDIM * CDIM, pwol + (size_t)l * CDIM * CDIM,
            ob + (size_t)l * CDIM, py, nullptr, nullptr, CDIM, CDIM);

        add_ln_kernel<true><<<NTOK, 256>>>(px, py,
            ln1g + (size_t)l * CDIM, ln1b + (size_t)l * CDIM, px,
            (uint32_t*)pxh, (uint32_t*)pxl);

        gemm_mma_kernel<true, true><<<dim3(FFD / 128, NTOK / 128), 256, G_SMEM>>>(
            pxh, pxl,
            pw1h + (size_t)l * FFD * CDIM, pw1l + (size_t)l * FFD * CDIM,
            b1 + (size_t)l * FFD, nullptr, (uint32_t*)pfh, (uint32_t*)pfl,
            CDIM, FFD);

        gemm_mma_kernel<false, false><<<dim3(CDIM / 128, NTOK / 128), 256, G_SMEM>>>(
            pfh, pfl,
            pw2h + (size_t)l * CDIM * FFD, pw2l + (size_t)l * CDIM * FFD,
            b2 + (size_t)l * CDIM, py, nullptr, nullptr, FFD, CDIM);

        if (l == NLAYER - 1) {
            add_ln_kernel<false><<<NTOK, 256>>>(px, py,
                ln2g + (size_t)l * CDIM, ln2b + (size_t)l * CDIM, out,
                nullptr, nullptr);
        } else {
            add_ln_kernel<true><<<NTOK, 256>>>(px, py,
                ln2g + (size_t)l * CDIM, ln2b + (size_t)l * CDIM, px,
                (uint32_t*)pxh, (uint32_t*)pxl);
        }
    }
}

// round 16
// speedup vs baseline: 1.0734x; 1.0016x over previous
#include <cuda_runtime.h>
#include <cstdint>

// ---------------------------------------------------------------------------
// Transformer encoder: split-bf16 mma.sync GEMMs (2 CTAs/SM) + fused flash
// attention (2 CTAs/SM via streamed-Q register diet), LPT CTA ordering.
// B=4, T=1024, C=1024, H=16, HD=64, FF=4096, L=4
// ---------------------------------------------------------------------------

#define NTOK   4096
#define CDIM   1024
#define QKVD   1536
#define KVOFF  1024
#define VOFF   1280
#define FFD    4096
#define TT     1024
#define NBH    64
#define HDIM   64
#define NLAYER 4

// ---- fp32 scratch ----
__device__ float g_x[NTOK * CDIM];
__device__ float g_y[NTOK * CDIM];

// ---- split-bf16 activation planes ----
__device__ uint16_t g_xh[NTOK * CDIM];
__device__ uint16_t g_xl[NTOK * CDIM];
__device__ uint16_t g_qh[NTOK * QKVD];
__device__ uint16_t g_ql[NTOK * QKVD];
__device__ uint16_t g_oh[NTOK * CDIM];
__device__ uint16_t g_ol[NTOK * CDIM];
__device__ uint16_t g_fh[NTOK * FFD];
__device__ uint16_t g_fl[NTOK * FFD];

// ---- split-bf16 weight planes ----
__device__ uint16_t g_wih[NLAYER * QKVD * CDIM];
__device__ uint16_t g_wil[NLAYER * QKVD * CDIM];
__device__ uint16_t g_woh[NLAYER * CDIM * CDIM];
__device__ uint16_t g_wol[NLAYER * CDIM * CDIM];
__device__ uint16_t g_w1h[NLAYER * FFD * CDIM];
__device__ uint16_t g_w1l[NLAYER * FFD * CDIM];
__device__ uint16_t g_w2h[NLAYER * CDIM * FFD];
__device__ uint16_t g_w2l[NLAYER * CDIM * FFD];

// ===========================================================================
// helpers
// ===========================================================================
__device__ __forceinline__ uint32_t smem_u32(const void* p) {
    uint32_t a;
    asm("{ .reg .u64 t; cvta.to.shared.u64 t, %1; cvt.u32.u64 %0, t; }"
        : "=r"(a) : "l"(p));
    return a;
}
__device__ __forceinline__ uint32_t f2bf_rn(float x) {
    uint32_t u = __float_as_uint(x);
    return (u + 0x7FFFu + ((u >> 16) & 1u)) >> 16;
}
__device__ __forceinline__ float bf2f(uint32_t h) {
    return __uint_as_float(h << 16);
}
__device__ __forceinline__ uint32_t pack_split(float a, float b, uint32_t* lo) {
    uint32_t ha = f2bf_rn(a), hb = f2bf_rn(b);
    *lo = f2bf_rn(a - bf2f(ha)) | (f2bf_rn(b - bf2f(hb)) << 16);
    return ha | (hb << 16);
}

#define CP16(dst, src) \
    asm volatile("cp.async.cg.shared.global [%0], [%1], 16;" \
                 :: "r"(dst), "l"(src))
#define CP_COMMIT() asm volatile("cp.async.commit_group;" ::: "memory")
#define CP_WAIT0()  asm volatile("cp.async.wait_group 0;" ::: "memory")
#define CP_WAIT1()  asm volatile("cp.async.wait_group 1;" ::: "memory")

__device__ __forceinline__ void ldsm4(uint32_t* r, uint32_t addr) {
    asm volatile("ldmatrix.sync.aligned.m8n8.x4.shared.b16 {%0,%1,%2,%3}, [%4];"
                 : "=r"(r[0]), "=r"(r[1]), "=r"(r[2]), "=r"(r[3]) : "r"(addr));
}
__device__ __forceinline__ void ldsm4t(uint32_t* r, uint32_t addr) {
    asm volatile("ldmatrix.sync.aligned.m8n8.x4.trans.shared.b16 {%0,%1,%2,%3}, [%4];"
                 : "=r"(r[0]), "=r"(r[1]), "=r"(r[2]), "=r"(r[3]) : "r"(addr));
}
__device__ __forceinline__ void mma_bf16(float* c, const uint32_t* a,
                                         const uint32_t* b) {
    asm volatile(
        "mma.sync.aligned.m16n8k16.row.col.f32.bf16.bf16.f32 "
        "{%0,%1,%2,%3}, {%4,%5,%6,%7}, {%8,%9}, {%0,%1,%2,%3};"
        : "+f"(c[0]), "+f"(c[1]), "+f"(c[2]), "+f"(c[3])
        : "r"(a[0]), "r"(a[1]), "r"(a[2]), "r"(a[3]), "r"(b[0]), "r"(b[1]));
}

// ===========================================================================
// split kernels
// ===========================================================================
__global__ __launch_bounds__(256) void split2_kernel(
    const float4* __restrict__ s1, int n1blocks,
    uint2* __restrict__ h1, uint2* __restrict__ l1,
    const float4* __restrict__ s2,
    uint2* __restrict__ h2, uint2* __restrict__ l2)
{
    int blk = blockIdx.x;
    const float4* src; uint2 *hi, *lo; size_t i;
    if (blk < n1blocks) {
        i = (size_t)blk * 256 + threadIdx.x; src = s1; hi = h1; lo = l1;
    } else {
        i = (size_t)(blk - n1blocks) * 256 + threadIdx.x;
        src = s2; hi = h2; lo = l2;
    }
    float4 v = src[i];
    uint32_t l0, l1r;
    uint32_t h0 = pack_split(v.x, v.y, &l0);
    uint32_t h1r = pack_split(v.z, v.w, &l1r);
    hi[i] = make_uint2(h0, h1r);
    lo[i] = make_uint2(l0, l1r);
}

__global__ __launch_bounds__(256) void copy_in_kernel(
    const float4* __restrict__ src, float4* __restrict__ dst,
    uint2* __restrict__ hi, uint2* __restrict__ lo)
{
    size_t i = (size_t)blockIdx.x * 256 + threadIdx.x;
    float4 v = src[i];
    dst[i] = v;
    uint32_t l0, l1;
    uint32_t h0 = pack_split(v.x, v.y, &l0);
    uint32_t h1 = pack_split(v.z, v.w, &l1);
    hi[i] = make_uint2(h0, h1);
    lo[i] = make_uint2(l0, l1);
}

// ===========================================================================
// mma.sync GEMM: CTA 128x128, warp tile 64x32, BK=32, 2-stage, split-bf16 x3,
// 2 CTAs/SM (regs capped at 128 — measured win in R13).
// ===========================================================================
#define G_STAGE 40960
#define G_SMEM  (2 * G_STAGE)

__device__ __forceinline__ void gemm_issue(
    uint32_t sb, int buf, int kb,
    const uint16_t* Ah, const uint16_t* Al,
    const uint16_t* Wh, const uint16_t* Wl,
    int row0, int col0, int K, int tid)
{
    uint32_t dst = sb + (uint32_t)buf * G_STAGE;
    int ch = tid & 3;
    size_t kbase = (size_t)kb * 32 + ch * 8;
#pragma unroll
    for (int i = 0; i < 2; i++) {
        int r = (tid >> 2) + i * 64;
        uint32_t so = (uint32_t)(r * 80 + ch * 16);
        CP16(dst + so,         Ah + (size_t)(row0 + r) * K + kbase);
        CP16(dst + 10240 + so, Al + (size_t)(row0 + r) * K + kbase);
        CP16(dst + 20480 + so, Wh + (size_t)(col0 + r) * K + kbase);
        CP16(dst + 30720 + so, Wl + (size_t)(col0 + r) * K + kbase);
    }
}

template <bool RELU, bool SPLIT>
__global__ __launch_bounds__(256, 2) void gemm_mma_kernel(
    const uint16_t* __restrict__ Ah, const uint16_t* __restrict__ Al,
    const uint16_t* __restrict__ Wh, const uint16_t* __restrict__ Wl,
    const float* __restrict__ bias, float* __restrict__ outf,
    uint32_t* __restrict__ outh, uint32_t* __restrict__ outl,
    int K, int N)
{
    extern __shared__ char sm[];
    const uint32_t sb = smem_u32(sm);
    const int tid = threadIdx.x, lane = tid & 31, wid = tid >> 5;
    const int row0 = blockIdx.y << 7, col0 = blockIdx.x << 7;
    const int m0 = (wid >> 2) << 6;
    const int n0 = (wid & 3) << 5;

    const uint32_t aoff = (uint32_t)((m0 + (lane & 15)) * 80 + (lane >> 4) * 16);
    const uint32_t boff = (uint32_t)((n0 + (lane & 7) + ((lane >> 4) & 1) * 8) * 80
                                     + ((lane >> 3) & 1) * 16);

    float acc[4][4][4];
#pragma unroll
    for (int mi = 0; mi < 4; mi++)
#pragma unroll
        for (int ni = 0; ni < 4; ni++)
#pragma unroll
            for (int q = 0; q < 4; q++) acc[mi][ni][q] = 0.f;

    const int nkb = K >> 5;
    gemm_issue(sb, 0, 0, Ah, Al, Wh, Wl, row0, col0, K, tid);
    CP_COMMIT();

    for (int kb = 0; kb < nkb; kb++) {
        CP_WAIT0();
        __syncthreads();
        if (kb + 1 < nkb) {
            gemm_issue(sb, (kb + 1) & 1, kb + 1, Ah, Al, Wh, Wl,
                       row0, col0, K, tid);
            CP_COMMIT();
        }
        const uint32_t base = sb + (uint32_t)(kb & 1) * G_STAGE;
#pragma unroll
        for (int ks = 0; ks < 2; ks++) {
            uint32_t fah[4][4], fal[4][4], fbh[2][4], fbl[2][4];
#pragma unroll
            for (int mi = 0; mi < 4; mi++) {
                uint32_t off = aoff + mi * 1280 + ks * 32;
                ldsm4(fah[mi], base + off);
                ldsm4(fal[mi], base + 10240 + off);
            }
#pragma unroll
            for (int nj = 0; nj < 2; nj++) {
                uint32_t off = boff + nj * 1280 + ks * 32;
                ldsm4(fbh[nj], base + 20480 + off);
                ldsm4(fbl[nj], base + 30720 + off);
            }
#pragma unroll
            for (int mi = 0; mi < 4; mi++) {
#pragma unroll
                for (int ni = 0; ni < 4; ni++) {
                    const uint32_t* bh = &fbh[ni >> 1][(ni & 1) * 2];
                    const uint32_t* bl = &fbl[ni >> 1][(ni & 1) * 2];
                    mma_bf16(acc[mi][ni], fah[mi], bh);
                    mma_bf16(acc[mi][ni], fah[mi], bl);
                    mma_bf16(acc[mi][ni], fal[mi], bh);
                }
            }
        }
        __syncthreads();
    }

#pragma unroll
    for (int mi = 0; mi < 4; mi++) {
        int row = row0 + m0 + mi * 16 + (lane >> 2);
#pragma unroll
        for (int ni = 0; ni < 4; ni++) {
            int col = col0 + n0 + ni * 8 + (lane & 3) * 2;
            float b0 = __ldg(&bias[col]), b1 = __ldg(&bias[col + 1]);
            float v00 = acc[mi][ni][0] + b0, v01 = acc[mi][ni][1] + b1;
            float v10 = acc[mi][ni][2] + b0, v11 = acc[mi][ni][3] + b1;
            if (RELU) {
                v00 = fmaxf(v00, 0.f); v01 = fmaxf(v01, 0.f);
                v10 = fmaxf(v10, 0.f); v11 = fmaxf(v11, 0.f);
            }
            if (SPLIT) {
                uint32_t l0, l1;
                uint32_t h0 = pack_split(v00, v01, &l0);
                uint32_t h1 = pack_split(v10, v11, &l1);
                size_t i0 = ((size_t)row * N + col) >> 1;
                size_t i1 = ((size_t)(row + 8) * N + col) >> 1;
                outh[i0] = h0; outl[i0] = l0;
                outh[i1] = h1; outl[i1] = l1;
            } else {
                *reinterpret_cast<float2*>(&outf[(size_t)row * N + col]) =
                    make_float2(v00, v01);
                *reinterpret_cast<float2*>(&outf[(size_t)(row + 8) * N + col]) =
                    make_float2(v10, v11);
            }
        }
    }
}

// ===========================================================================
// fused flash attention, LPT ordering, 2 CTAs/SM.
// Q fragments streamed from smem per k-chunk (saves 32 persistent regs so
// the (256,2) cap fits: smem 2x110.6KB = 221KB < 228KB carveout).
// ===========================================================================
#define SKS      144
#define FL_QL    18432
#define FL_ST0   36864
#define FL_STAGE 36864
#define FL_SMEM  (FL_ST0 + 2 * FL_STAGE)
#define SCL      0.1803368801111204f   // 0.125 * log2(e)

__device__ __forceinline__ void flash_issue_kv(
    uint32_t sb, int buf, int s0, int b, int kvh, int tid,
    const uint16_t* Qhp, const uint16_t* Qlp)
{
    uint32_t dst = sb + FL_ST0 + (uint32_t)buf * FL_STAGE;
    int r = tid >> 2;
    int c0 = (tid & 3) * 2;
    size_t rowoff = (size_t)(b * TT + s0 + r) * QKVD;
    const uint16_t* kh = Qhp + rowoff + KVOFF + kvh * HDIM;
    const uint16_t* kl = Qlp + rowoff + KVOFF + kvh * HDIM;
    const uint16_t* vh = Qhp + rowoff + VOFF + kvh * HDIM;
    const uint16_t* vl = Qlp + rowoff + VOFF + kvh * HDIM;
    uint32_t so = (uint32_t)(r * SKS + c0 * 16);
#pragma unroll
    for (int c = 0; c < 2; c++) {
        CP16(dst + so + c * 16,         kh + (c0 + c) * 8);
        CP16(dst + 9216 + so + c * 16,  kl + (c0 + c) * 8);
        CP16(dst + 18432 + so + c * 16, vh + (c0 + c) * 8);
        CP16(dst + 27648 + so + c * 16, vl + (c0 + c) * 8);
    }
}

__global__ __launch_bounds__(256, 2) void flash_kernel(
    const uint16_t* __restrict__ Qhp, const uint16_t* __restrict__ Qlp,
    uint32_t* __restrict__ Oh, uint32_t* __restrict__ Ol)
{
    extern __shared__ char sm[];
    const uint32_t sb = smem_u32(sm);
    const int tid = threadIdx.x, lane = tid & 31, wid = tid >> 5;
    const int bh = blockIdx.y, b = bh >> 4, hq = bh & 15, kvh = hq & 3;
    const int xr = (int)gridDim.x - 1 - (int)blockIdx.x;
    const int q0 = xr * 128;
    const int iters = 2 * (xr + 1);

    {
        int r = tid >> 1;
        int cb = (tid & 1) * 4;
        size_t src = (size_t)(b * TT + q0 + r) * QKVD + hq * HDIM + cb * 8;
        uint32_t d0 = sb + r * SKS + cb * 16;
#pragma unroll
        for (int c = 0; c < 4; c++) {
            CP16(d0 + c * 16,          Qhp + src + c * 8);
            CP16(d0 + FL_QL + c * 16,  Qlp + src + c * 8);
        }
    }
    flash_issue_kv(sb, 0, 0, b, kvh, tid, Qhp, Qlp);
    CP_COMMIT();
    if (iters > 1) {
        flash_issue_kv(sb, 1, 64, b, kvh, tid, Qhp, Qlp);
        CP_COMMIT();
        CP_WAIT1();
    } else {
        CP_WAIT0();
    }
    __syncthreads();

    // per-warp Q ldsm base (fragments streamed per k-chunk inside the loop)
    const uint32_t qa = sb + (uint32_t)((wid * 16 + (lane & 15)) * SKS
                                        + (lane >> 4) * 16);

    float o[8][4];
#pragma unroll
    for (int j = 0; j < 8; j++)
#pragma unroll
        for (int q = 0; q < 4; q++) o[j][q] = 0.f;
    float mA = -1e30f, mB = -1e30f, lA = 0.f, lB = 0.f;

    const int qA = q0 + wid * 16 + (lane >> 2);
    const int qB = qA + 8;

    for (int it = 0; it < iters; it++) {
        const int s0 = it * 64;
        const uint32_t base = sb + FL_ST0 + (uint32_t)(it & 1) * FL_STAGE;

        float sc[8][4];
#pragma unroll
        for (int j = 0; j < 8; j++)
#pragma unroll
            for (int q = 0; q < 4; q++) sc[j][q] = 0.f;

        const uint32_t kb0 = (uint32_t)(((lane & 7) + ((lane >> 4) & 1) * 8) * SKS
                                        + ((lane >> 3) & 1) * 16);
#pragma unroll
        for (int t = 0; t < 4; t++) {
            uint32_t qh_t[4], ql_t[4];
            ldsm4(qh_t, qa + t * 32);
            ldsm4(ql_t, qa + FL_QL + t * 32);
            uint32_t kh[4][4], kl[4][4];
#pragma unroll
            for (int p = 0; p < 4; p++) {
                uint32_t off = kb0 + (uint32_t)(p * 16 * SKS) + t * 32;
                ldsm4(kh[p], base + off);
                ldsm4(kl[p], base + 9216 + off);
            }
#pragma unroll
            for (int j = 0; j < 8; j++) {
                const uint32_t* bhp = &kh[j >> 1][(j & 1) * 2];
                const uint32_t* blp = &kl[j >> 1][(j & 1) * 2];
                mma_bf16(sc[j], qh_t, bhp);
                mma_bf16(sc[j], qh_t, blp);
                mma_bf16(sc[j], ql_t, bhp);
            }
        }

#pragma unroll
        for (int j = 0; j < 8; j++) {
            int s = s0 + j * 8 + (lane & 3) * 2;
            sc[j][0] = (s     <= qA) ? sc[j][0] : -1e30f;
            sc[j][1] = (s + 1 <= qA) ? sc[j][1] : -1e30f;
            sc[j][2] = (s     <= qB) ? sc[j][2] : -1e30f;
            sc[j][3] = (s + 1 <= qB) ? sc[j][3] : -1e30f;
        }

        float tmA = -1e30f, tmB = -1e30f;
#pragma unroll
        for (int j = 0; j < 8; j++) {
            tmA = fmaxf(tmA, fmaxf(sc[j][0], sc[j][1]));
            tmB = fmaxf(tmB, fmaxf(sc[j][2], sc[j][3]));
        }
        tmA = fmaxf(tmA, __shfl_xor_sync(0xffffffffu, tmA, 1));
        tmA = fmaxf(tmA, __shfl_xor_sync(0xffffffffu, tmA, 2));
        tmB = fmaxf(tmB, __shfl_xor_sync(0xffffffffu, tmB, 1));
        tmB = fmaxf(tmB, __shfl_xor_sync(0xffffffffu, tmB, 2));
        float nmA = fmaxf(mA, tmA), nmB = fmaxf(mB, tmB);
        float aA = exp2f((mA - nmA) * SCL);
        float aB = exp2f((mB - nmB) * SCL);
        mA = nmA; mB = nmB;
        float nAs = nmA * SCL, nBs = nmB * SCL;

        float sumA = 0.f, sumB = 0.f;
#pragma unroll
        for (int j = 0; j < 8; j++) {
            sc[j][0] = exp2f(fmaf(sc[j][0], SCL, -nAs));
            sc[j][1] = exp2f(fmaf(sc[j][1], SCL, -nAs));
            sc[j][2] = exp2f(fmaf(sc[j][2], SCL, -nBs));
            sc[j][3] = exp2f(fmaf(sc[j][3], SCL, -nBs));
            sumA += sc[j][0] + sc[j][1];
            sumB += sc[j][2] + sc[j][3];
        }
        sumA += __shfl_xor_sync(0xffffffffu, sumA, 1);
        sumA += __shfl_xor_sync(0xffffffffu, sumA, 2);
        sumB += __shfl_xor_sync(0xffffffffu, sumB, 1);
        sumB += __shfl_xor_sync(0xffffffffu, sumB, 2);
        lA = lA * aA + sumA;
        lB = lB * aB + sumB;
#pragma unroll
        for (int j = 0; j < 8; j++) {
            o[j][0] *= aA; o[j][1] *= aA;
            o[j][2] *= aB; o[j][3] *= aB;
        }

        const uint32_t vb0 = (uint32_t)(((lane & 7) + ((lane >> 3) & 1) * 8) * SKS
                                        + ((lane >> 4) & 1) * 16);
#pragma unroll
        for (int t = 0; t < 4; t++) {
            uint32_t ah[4], al[4];
            ah[0] = pack_split(sc[2 * t][0],     sc[2 * t][1],     &al[0]);
            ah[1] = pack_split(sc[2 * t][2],     sc[2 * t][3],     &al[1]);
            ah[2] = pack_split(sc[2 * t + 1][0], sc[2 * t + 1][1], &al[2]);
            ah[3] = pack_split(sc[2 * t + 1][2], sc[2 * t + 1][3], &al[3]);
            uint32_t vh[4][4], vl[4][4];
#pragma unroll
            for (int p = 0; p < 4; p++) {
                uint32_t off = vb0 + (uint32_t)(t * 16 * SKS) + p * 32;
                ldsm4t(vh[p], base + 18432 + off);
                ldsm4t(vl[p], base + 27648 + off);
            }
#pragma unroll
            for (int j = 0; j < 8; j++) {
                const uint32_t* bhp = &vh[j >> 1][(j & 1) * 2];
                const uint32_t* blp = &vl[j >> 1][(j & 1) * 2];
                mma_bf16(o[j], ah, bhp);
                mma_bf16(o[j], ah, blp);
                mma_bf16(o[j], al, bhp);
            }
        }

        __syncthreads();
        if (it + 2 < iters) {
            flash_issue_kv(sb, it & 1, (it + 2) * 64, b, kvh, tid, Qhp, Qlp);
            CP_COMMIT();
        }
        if (it + 1 < iters) {
            if (it + 2 < iters) CP_WAIT1(); else CP_WAIT0();
            __syncthreads();
        }
    }

    float rA = 1.f / lA, rB = 1.f / lB;
    size_t tokA = (size_t)(b * TT + q0 + wid * 16 + (lane >> 2));
    size_t tokB = tokA + 8;
#pragma unroll
    for (int j = 0; j < 8; j++) {
        int col = hq * HDIM + j * 8 + (lane & 3) * 2;
        uint32_t l0, l1;
        uint32_t h0 = pack_split(o[j][0] * rA, o[j][1] * rA, &l0);
        uint32_t h1 = pack_split(o[j][2] * rB, o[j][3] * rB, &l1);
        size_t i0 = (tokA * CDIM + col) >> 1;
        size_t i1 = (tokB * CDIM + col) >> 1;
        Oh[i0] = h0; Ol[i0] = l0;
        Oh[i1] = h1; Ol[i1] = l1;
    }
}

// ===========================================================================
// add + LayerNorm
// ===========================================================================
template <bool SPLIT>
__global__ __launch_bounds__(256) void add_ln_kernel(
    const float* __restrict__ resid, const float* __restrict__ delta,
    const float* __restrict__ gamma, const float* __restrict__ beta,
    float* __restrict__ out, uint32_t* __restrict__ oh,
    uint32_t* __restrict__ ol)
{
    size_t row = blockIdx.x;
    int tid = threadIdx.x;

    float4 rv = reinterpret_cast<const float4*>(resid + row * CDIM)[tid];
    float4 dv = reinterpret_cast<const float4*>(delta + row * CDIM)[tid];
    float v0 = rv.x + dv.x, v1 = rv.y + dv.y, v2 = rv.z + dv.z, v3 = rv.w + dv.w;

    __shared__ float rs[256], rss[256];
    rs[tid]  = v0 + v1 + v2 + v3;
    rss[tid] = v0 * v0 + v1 * v1 + v2 * v2 + v3 * v3;
    __syncthreads();
    for (int s = 128; s > 0; s >>= 1) {
        if (tid < s) { rs[tid] += rs[tid + s]; rss[tid] += rss[tid + s]; }
        __syncthreads();
    }
    float mu  = rs[0]  * (1.f / CDIM);
    float var = rss[0] * (1.f / CDIM) - mu * mu;
    float inv = rsqrtf(var + 1e-5f);

    float4 g  = reinterpret_cast<const float4*>(gamma)[tid];
    float4 bb = reinterpret_cast<const float4*>(beta)[tid];
    float4 ov;
    ov.x = (v0 - mu) * inv * g.x + bb.x;
    ov.y = (v1 - mu) * inv * g.y + bb.y;
    ov.z = (v2 - mu) * inv * g.z + bb.z;
    ov.w = (v3 - mu) * inv * g.w + bb.w;
    reinterpret_cast<float4*>(out + row * CDIM)[tid] = ov;
    if (SPLIT) {
        uint32_t l0, l1;
        uint32_t h0 = pack_split(ov.x, ov.y, &l0);
        uint32_t h1 = pack_split(ov.z, ov.w, &l1);
        size_t i0 = (row * CDIM) / 2 + tid * 2;
        oh[i0] = h0; ol[i0] = l0;
        oh[i0 + 1] = h1; ol[i0 + 1] = l1;
    }
}

// ===========================================================================
extern "C" void kernel_launch(void* const* d_in, const int* in_sizes, int n_in,
                              void* d_out, int out_size)
{
    const float* x    = (const float*)d_in[0];
    const float* ipw  = (const float*)d_in[1];
    const float* ipb  = (const float*)d_in[2];
    const float* ow   = (const float*)d_in[3];
    const float* ob   = (const float*)d_in[4];
    const float* w1   = (const float*)d_in[5];
    const float* b1   = (const float*)d_in[6];
    const float* w2   = (const float*)d_in[7];
    const float* b2   = (const float*)d_in[8];
    const float* ln1g = (const float*)d_in[9];
    const float* ln1b = (const float*)d_in[10];
    const float* ln2g = (const float*)d_in[11];
    const float* ln2b = (const float*)d_in[12];
    float* out = (float*)d_out;

    float *px, *py;
    uint16_t *pxh, *pxl, *pqh, *pql, *poh, *pol, *pfh, *pfl;
    uint16_t *pwih, *pwil, *pwoh, *pwol, *pw1h, *pw1l, *pw2h, *pw2l;
    cudaGetSymbolAddress((void**)&px,   g_x);
    cudaGetSymbolAddress((void**)&py,   g_y);
    cudaGetSymbolAddress((void**)&pxh,  g_xh);
    cudaGetSymbolAddress((void**)&pxl,  g_xl);
    cudaGetSymbolAddress((void**)&pqh,  g_qh);
    cudaGetSymbolAddress((void**)&pql,  g_ql);
    cudaGetSymbolAddress((void**)&poh,  g_oh);
    cudaGetSymbolAddress((void**)&pol,  g_ol);
    cudaGetSymbolAddress((void**)&pfh,  g_fh);
    cudaGetSymbolAddress((void**)&pfl,  g_fl);
    cudaGetSymbolAddress((void**)&pwih, g_wih);
    cudaGetSymbolAddress((void**)&pwil, g_wil);
    cudaGetSymbolAddress((void**)&pwoh, g_woh);
    cudaGetSymbolAddress((void**)&pwol, g_wol);
    cudaGetSymbolAddress((void**)&pw1h, g_w1h);
    cudaGetSymbolAddress((void**)&pw1l, g_w1l);
    cudaGetSymbolAddress((void**)&pw2h, g_w2h);
    cudaGetSymbolAddress((void**)&pw2l, g_w2l);

    cudaFuncSetAttribute(gemm_mma_kernel<false, false>,
                         cudaFuncAttributeMaxDynamicSharedMemorySize, G_SMEM);
    cudaFuncSetAttribute(gemm_mma_kernel<false, true>,
                         cudaFuncAttributeMaxDynamicSharedMemorySize, G_SMEM);
    cudaFuncSetAttribute(gemm_mma_kernel<true, true>,
                         cudaFuncAttributeMaxDynamicSharedMemorySize, G_SMEM);
    cudaFuncSetAttribute(flash_kernel,
                         cudaFuncAttributeMaxDynamicSharedMemorySize, FL_SMEM);

    copy_in_kernel<<<NTOK * CDIM / 1024, 256>>>(
        (const float4*)x, (float4*)px, (uint2*)pxh, (uint2*)pxl);
    split2_kernel<<<(NLAYER * QKVD * CDIM + NLAYER * CDIM * CDIM) / 1024, 256>>>(
        (const float4*)ipw, NLAYER * QKVD * CDIM / 1024,
        (uint2*)pwih, (uint2*)pwil,
        (const float4*)ow, (uint2*)pwoh, (uint2*)pwol);
    split2_kernel<<<2 * NLAYER * FFD * CDIM / 1024, 256>>>(
        (const float4*)w1, NLAYER * FFD * CDIM / 1024,
        (uint2*)pw1h, (uint2*)pw1l,
        (const float4*)w2, (uint2*)pw2h, (uint2*)pw2l);

    for (int l = 0; l < NLAYER; l++) {
        gemm_mma_kernel<false, true><<<dim3(QKVD / 128, NTOK / 128), 256, G_SMEM>>>(
            pxh, pxl,
            pwih + (size_t)l * QKVD * CDIM, pwil + (size_t)l * QKVD * CDIM,
            ipb + (size_t)l * QKVD, nullptr, (uint32_t*)pqh, (uint32_t*)pql,
            CDIM, QKVD);

        flash_kernel<<<dim3(TT / 128, NBH), 256, FL_SMEM>>>(
            pqh, pql, (uint32_t*)poh, (uint32_t*)pol);

        gemm_mma_kernel<false, false><<<dim3(CDIM / 128, NTOK / 128), 256, G_SMEM>>>(
            poh, pol,
            pwoh + (size_t)l * CDIM * CDIM, pwol + (size_t)l * CDIM * CDIM,
            ob + (size_t)l * CDIM, py, nullptr, nullptr, CDIM, CDIM);

        add_ln_kernel<true><<<NTOK, 256>>>(px, py,
            ln1g + (size_t)l * CDIM, ln1b + (size_t)l * CDIM, px,
            (uint32_t*)pxh, (uint32_t*)pxl);

        gemm_mma_kernel<true, true><<<dim3(FFD / 128, NTOK / 128), 256, G_SMEM>>>(
            pxh, pxl,
            pw1h + (size_t)l * FFD * CDIM, pw1l + (size_t)l * FFD * CDIM,
            b1 + (size_t)l * FFD, nullptr, (uint32_t*)pfh, (uint32_t*)pfl,
            CDIM, FFD);

        gemm_mma_kernel<false, false><<<dim3(CDIM / 128, NTOK / 128), 256, G_SMEM>>>(
            pfh, pfl,
            pw2h + (size_t)l * CDIM * FFD, pw2l + (size_t)l * CDIM * FFD,
            b2 + (size_t)l * CDIM, py, nullptr, nullptr, FFD, CDIM);

        if (l == NLAYER - 1) {
            add_ln_kernel<false><<<NTOK, 256>>>(px, py,
                ln2g + (size_t)l * CDIM, ln2b + (size_t)l * CDIM, out,
                nullptr, nullptr);
        } else {
            add_ln_kernel<true><<<NTOK, 256>>>(px, py,
                ln2g + (size_t)l * CDIM, ln2b + (size_t)l * CDIM, px,
                (uint32_t*)pxh, (uint32_t*)pxl);
        }
    }
}